// round 3
// baseline (speedup 1.0000x reference)
#include <cuda_runtime.h>
#include <math.h>

// ---------------- Problem constants ----------------
#define Bn 8
#define Dn 64
#define Hn 256
#define Wn 256
#define Kn 49
#define HWn (Hn*Wn)
#define Pn (Bn*HWn)             // 524288 pixels

// ---------------- Tiling ----------------
#define TX 32                   // tile width (pixels)
#define TY 16                   // tile height
#define HX 38                   // halo width  (TX+6)
#define HY 22                   // halo height (TY+6)
#define HXP 40                  // padded vis pitch (even, LDS.64-aligned, conflict-free)
#define TXP 34                  // padded rubin pitch
#define DC 4                    // channels per chunk
#define NCH (Dn/DC)             // 16 chunks

#define NVV (HY*HX)             // 836 vis vectors per tile
#define VIS_ELE (DC*HY*HXP)     // 3520 floats
#define RUB_ELE (DC*TY*TXP)     // 2176 floats
#define BUF_ELE (VIS_ELE+RUB_ELE) // 5696
#define VIS_REAL (DC*HY*HX)     // 3344
#define RUB_REAL (DC*TY*TX)     // 2048

#define TILES_X (Wn/TX)         // 8
#define TILES_Y (Hn/TY)         // 16
#define TILES_PER_B (TILES_X*TILES_Y)  // 128
#define NBLK (Bn*TILES_PER_B)   // 1024

// ---------------- Output layout (flattened tuple concat) ----------------
#define OFF_DY 0
#define OFF_DX ((size_t)Pn)
#define OFF_CL ((size_t)2*Pn)
#define OFF_CG ((size_t)3*Pn)
#define OFF_LW ((size_t)3*Pn+8)
#define OFF_LG ((size_t)4*Pn+8)

// ---------------- Scratch (device globals; no allocation allowed) ----------------
__device__ float g_part[NBLK*Kn];
__device__ float g_dyg[Bn];
__device__ float g_dxg[Bn];

__device__ __forceinline__ void cpa4(float* smem_dst, const float* gsrc) {
    unsigned s = (unsigned)__cvta_generic_to_shared(smem_dst);
    asm volatile("cp.async.ca.shared.global [%0], [%1], 4;" :: "r"(s), "l"(gsrc));
}

// Stage one D-chunk (vis halo with edge clamp + rubin tile) into smem via cp.async
__device__ __forceinline__ void stage_chunk(float* __restrict__ buf,
        const float* __restrict__ rubin, const float* __restrict__ vis,
        int b, int d0, int x0, int y0, int tid)
{
    const float* visb = vis + (size_t)(b*Dn + d0)*HWn;
    #pragma unroll 1
    for (int i = tid; i < VIS_REAL; i += 256) {
        int d   = i / (HY*HX);
        int rem = i - d*(HY*HX);
        int r   = rem / HX;
        int c   = rem - r*HX;
        int gy = y0 - 3 + r; gy = max(0, min(Hn-1, gy));
        int gx = x0 - 3 + c; gx = max(0, min(Wn-1, gx));
        cpa4(buf + d*(HY*HXP) + r*HXP + c, visb + (size_t)d*HWn + gy*Wn + gx);
    }
    const float* rubb = rubin + (size_t)(b*Dn + d0)*HWn + (size_t)y0*Wn + x0;
    float* rbuf = buf + VIS_ELE;
    #pragma unroll 1
    for (int i = tid; i < RUB_REAL; i += 256) {
        int d = i >> 9;            // / (TY*TX) = 512
        int r = (i >> 5) & (TY-1);
        int c = i & (TX-1);
        cpa4(rbuf + d*(TY*TXP) + r*TXP + c, rubb + (size_t)d*HWn + r*Wn + c);
    }
}

// Accumulate raw dots for one D-chunk; also rubin sumsq and owned vis sumsq
__device__ __forceinline__ void compute_chunk(const float* __restrict__ buf,
        int ty, int tx2,
        float (&acc0)[Kn], float (&acc1)[Kn],
        float& ss0, float& ss1,
        float (&vss)[4], const int (&voff)[4], int nvo)
{
    const float* rub = buf + VIS_ELE;
    #pragma unroll
    for (int d = 0; d < DC; ++d) {
        const float* rrow = rub + d*(TY*TXP) + ty*TXP + tx2;
        float ru0 = rrow[0];
        float ru1 = rrow[1];
        ss0 = fmaf(ru0, ru0, ss0);
        ss1 = fmaf(ru1, ru1, ss1);
        const float* vplane = buf + d*(HY*HXP);
        #pragma unroll
        for (int r = 0; r < 7; ++r) {
            const float* vr = vplane + (ty + r)*HXP + tx2;
            float v[8];
            #pragma unroll
            for (int c = 0; c < 8; ++c) v[c] = vr[c];
            #pragma unroll
            for (int c = 0; c < 8; ++c) {
                if (c < 7) acc0[r*7 + c]     = fmaf(ru0, v[c], acc0[r*7 + c]);
                if (c > 0) acc1[r*7 + c - 1] = fmaf(ru1, v[c], acc1[r*7 + c - 1]);
            }
        }
    }
    // vis sumsq for halo vectors owned by this thread
    #pragma unroll
    for (int j = 0; j < 4; ++j) {
        if (j < nvo) {
            float s = vss[j];
            #pragma unroll
            for (int d = 0; d < DC; ++d) {
                float v = buf[d*(HY*HXP) + voff[j]];
                s = fmaf(v, v, s);
            }
            vss[j] = s;
        }
    }
}

__device__ __forceinline__ void pixel_post(const float (&l)[Kn], float itau,
        float& dyl, float& dxl, float& conf)
{
    float m = l[0];
    #pragma unroll
    for (int k = 1; k < Kn; ++k) m = fmaxf(m, l[k]);
    float s = 0.f, wy = 0.f, wx = 0.f;
    #pragma unroll
    for (int k = 0; k < Kn; ++k) {
        float e = __expf((l[k] - m)*itau);
        s += e;
        wy += e * (float)(k/7 - 3);
        wx += e * (float)(k%7 - 3);
    }
    float is = 1.f/s;
    conf = is;          // exp(0)=1 at the max -> max prob = 1/sum
    dyl = wy*is;
    dxl = wx*is;
}

__global__ void __launch_bounds__(256)
ccb_main_kernel(const float* __restrict__ rubin, const float* __restrict__ vis,
                const float* __restrict__ logt, float* __restrict__ out)
{
    __shared__ float sm[2*BUF_ELE];
    float* buf0 = sm;
    float* buf1 = sm + BUF_ELE;
    // aliases onto buf0, used only after the main loop:
    float* vinv  = sm;            // HY*HXP = 880 floats
    float* sredw = sm + 880;      // 8 warps * 49 = 392 floats

    const int tx = threadIdx.x, ty = threadIdx.y;
    const int tid = ty*16 + tx;
    const int x0 = blockIdx.x*TX, y0 = blockIdx.y*TY, b = blockIdx.z;
    const int tx2 = 2*tx;

    float acc0[Kn], acc1[Kn];
    #pragma unroll
    for (int k = 0; k < Kn; ++k) { acc0[k] = 0.f; acc1[k] = 0.f; }
    float ss0 = 0.f, ss1 = 0.f;
    float vss[4] = {0.f, 0.f, 0.f, 0.f};
    const int nvo = (tid < (NVV - 3*256)) ? 4 : 3;   // 836 = 3*256 + 68
    int voff[4];
    #pragma unroll
    for (int j = 0; j < 4; ++j) {
        int v = tid + 256*j;
        int row = v / HX;
        voff[j] = row*HXP + (v - row*HX);
    }

    // Software-pipelined chunk loop (cp.async double buffer)
    stage_chunk(buf0, rubin, vis, b, 0, x0, y0, tid);
    asm volatile("cp.async.commit_group;" ::: "memory");
    #pragma unroll 1
    for (int ch = 0; ch < NCH; ++ch) {
        if (ch + 1 < NCH) {
            stage_chunk(((ch+1) & 1) ? buf1 : buf0, rubin, vis, b, (ch+1)*DC, x0, y0, tid);
            asm volatile("cp.async.commit_group;" ::: "memory");
            asm volatile("cp.async.wait_group 1;" ::: "memory");
        } else {
            asm volatile("cp.async.wait_group 0;" ::: "memory");
        }
        __syncthreads();
        compute_chunk((ch & 1) ? buf1 : buf0, ty, tx2, acc0, acc1, ss0, ss1, vss, voff, nvo);
        __syncthreads();
    }

    // Inverse norms (matches reference: x / max(|x|, 1e-6))
    float inv0 = 1.f / fmaxf(sqrtf(ss0), 1e-6f);
    float inv1 = 1.f / fmaxf(sqrtf(ss1), 1e-6f);
    #pragma unroll
    for (int j = 0; j < 4; ++j)
        if (j < nvo) vinv[voff[j]] = 1.f / fmaxf(sqrtf(vss[j]), 1e-6f);
    __syncthreads();

    // Finalize logits: raw_dot * inv|r| * inv|v| * (1/sqrt(D))
    const float s0 = inv0 * 0.125f;
    const float s1 = inv1 * 0.125f;
    #pragma unroll
    for (int r = 0; r < 7; ++r) {
        const float* vr = vinv + (ty + r)*HXP + tx2;
        #pragma unroll
        for (int c = 0; c < 8; ++c) {
            float vi = vr[c];
            if (c < 7) acc0[r*7 + c]     *= s0 * vi;
            if (c > 0) acc1[r*7 + c - 1] *= s1 * vi;
        }
    }

    // Write logits (B,K,H,W), coalesced float2 per k
    {
        const size_t base = OFF_LG + (size_t)b*Kn*HWn + (size_t)(y0+ty)*Wn + (x0 + tx2);
        #pragma unroll
        for (int k = 0; k < Kn; ++k) {
            float2 v2 = make_float2(acc0[k], acc1[k]);
            *(float2*)(out + base + (size_t)k*HWn) = v2;
        }
    }

    // Deterministic per-block per-k sums for the global mean
    {
        const int lane = tid & 31, w = tid >> 5;
        #pragma unroll
        for (int k = 0; k < Kn; ++k) {
            float s = acc0[k] + acc1[k];
            s += __shfl_down_sync(0xffffffffu, s, 16);
            s += __shfl_down_sync(0xffffffffu, s, 8);
            s += __shfl_down_sync(0xffffffffu, s, 4);
            s += __shfl_down_sync(0xffffffffu, s, 2);
            s += __shfl_down_sync(0xffffffffu, s, 1);
            if (lane == 0) sredw[w*Kn + k] = s;
        }
        __syncthreads();
        if (tid < Kn) {
            float t = 0.f;
            #pragma unroll
            for (int w2 = 0; w2 < 8; ++w2) t += sredw[w2*Kn + tid];
            int blk = (b*TILES_Y + blockIdx.y)*TILES_X + blockIdx.x;
            g_part[(size_t)blk*Kn + tid] = t;
        }
    }

    // Local softmax / dy / dx / conf / local_weight
    const float tau  = fmaxf(__expf(logt[0]), 1e-3f);
    const float itau = 1.f / tau;
    const float uni  = 1.0f / (float)Kn;
    const float ilw  = 1.0f / (1.0f - uni);

    float dyl0, dxl0, cf0, dyl1, dxl1, cf1;
    pixel_post(acc0, itau, dyl0, dxl0, cf0);
    pixel_post(acc1, itau, dyl1, dxl1, cf1);

    float lw0 = fminf(fmaxf((cf0 - uni)*ilw, 0.f), 1.f);
    float lw1 = fminf(fmaxf((cf1 - uni)*ilw, 0.f), 1.f);

    const size_t pix = (size_t)b*HWn + (size_t)(y0+ty)*Wn + (x0 + tx2);
    *(float2*)(out + OFF_DY + pix) = make_float2(dyl0, dyl1);  // local for now; blended by kernel 3
    *(float2*)(out + OFF_DX + pix) = make_float2(dxl0, dxl1);
    *(float2*)(out + OFF_CL + pix) = make_float2(cf0, cf1);
    *(float2*)(out + OFF_LW + pix) = make_float2(lw0, lw1);
}

__global__ void ccb_global_kernel(const float* __restrict__ logt, float* __restrict__ out)
{
    const int b = blockIdx.x;
    const int tid = threadIdx.x;   // 64 threads
    __shared__ float lg[Kn];
    if (tid < Kn) {
        float s = 0.f;
        const float* p = g_part + (size_t)(b*TILES_PER_B)*Kn + tid;
        #pragma unroll 4
        for (int t = 0; t < TILES_PER_B; ++t) s += p[(size_t)t*Kn];
        lg[tid] = s * (1.0f/(float)HWn);
    }
    __syncthreads();
    if (tid == 0) {
        const float tau  = fmaxf(__expf(logt[0]), 1e-3f);
        const float itau = 1.f / tau;
        float m = lg[0];
        #pragma unroll
        for (int k = 1; k < Kn; ++k) m = fmaxf(m, lg[k]);
        float s = 0.f, wy = 0.f, wx = 0.f;
        #pragma unroll
        for (int k = 0; k < Kn; ++k) {
            float e = __expf((lg[k] - m)*itau);
            s += e;
            wy += e * (float)(k/7 - 3);
            wx += e * (float)(k%7 - 3);
        }
        float is = 1.f/s;
        out[OFF_CG + b] = is;       // conf_global
        g_dyg[b] = wy*is;
        g_dxg[b] = wx*is;
    }
}

__global__ void ccb_blend_kernel(float* __restrict__ out)
{
    int i = blockIdx.x*blockDim.x + threadIdx.x;
    if (i >= Pn) return;
    int b = i >> 16;               // HWn = 65536
    float lw = out[OFF_LW + i];
    float gw = 1.0f - lw;
    float dyg = g_dyg[b], dxg = g_dxg[b];
    out[OFF_DY + i] = lw*out[OFF_DY + i] + gw*dyg;
    out[OFF_DX + i] = lw*out[OFF_DX + i] + gw*dxg;
}

extern "C" void kernel_launch(void* const* d_in, const int* in_sizes, int n_in,
                              void* d_out, int out_size) {
    const float* rubin = (const float*)d_in[0];
    const float* vis   = (const float*)d_in[1];
    const float* logt  = (const float*)d_in[2];
    float* out = (float*)d_out;
    (void)in_sizes; (void)n_in; (void)out_size;

    dim3 grid(TILES_X, TILES_Y, Bn);
    dim3 blk(16, 16, 1);
    ccb_main_kernel<<<grid, blk>>>(rubin, vis, logt, out);
    ccb_global_kernel<<<Bn, 64>>>(logt, out);
    ccb_blend_kernel<<<Pn/256, 256>>>(out);
}

// round 4
// speedup vs baseline: 1.9673x; 1.9673x over previous
#include <cuda_runtime.h>
#include <math.h>

// ---------------- Problem constants ----------------
#define Bn 8
#define Dn 64
#define Hn 256
#define Wn 256
#define Kn 49
#define HWn (Hn*Wn)
#define Pn (Bn*HWn)             // 524288 pixels

// ---------------- Tiling ----------------
#define TX 32                   // tile width (pixels)
#define TY 16                   // tile height
#define HX 38                   // halo width  (TX+6)
#define HY 22                   // halo height (TY+6)
#define HXP 40                  // padded vis pitch (8B-aligned rows, conflict-free LDS.64)
#define TXP 36                  // padded rubin pitch (16B-aligned rows for cp.async.16)
#define DC 4                    // channels per chunk
#define NCH (Dn/DC)             // 16 chunks

#define NVV (HY*HX)             // 836 vis halo vectors per tile
#define VIS_ELE (DC*HY*HXP)     // 3520 floats
#define RUB_ELE (DC*TY*TXP)     // 2304 floats
#define BUF_ELE (VIS_ELE+RUB_ELE) // 5824 floats; x2 buffers = 46592 B < 48KB

#define TILES_X (Wn/TX)         // 8
#define TILES_Y (Hn/TY)         // 16
#define TILES_PER_B (TILES_X*TILES_Y)  // 128
#define NBLK (Bn*TILES_PER_B)   // 1024

// ---------------- Output layout (flattened tuple concat) ----------------
#define OFF_DY 0
#define OFF_DX ((size_t)Pn)
#define OFF_CL ((size_t)2*Pn)
#define OFF_CG ((size_t)3*Pn)
#define OFF_LW ((size_t)3*Pn+8)
#define OFF_LG ((size_t)4*Pn+8)

// ---------------- Scratch (device globals; no allocation allowed) ----------------
__device__ float g_part[NBLK*Kn];
__device__ float g_dyg[Bn];
__device__ float g_dxg[Bn];

__device__ __forceinline__ void cpa4(float* smem_dst, const float* gsrc) {
    unsigned s = (unsigned)__cvta_generic_to_shared(smem_dst);
    asm volatile("cp.async.ca.shared.global [%0], [%1], 4;" :: "r"(s), "l"(gsrc));
}
__device__ __forceinline__ void cpa16(float* smem_dst, const float* gsrc) {
    unsigned s = (unsigned)__cvta_generic_to_shared(smem_dst);
    asm volatile("cp.async.cg.shared.global [%0], [%1], 16;" :: "r"(s), "l"(gsrc));
}

// Stage one D-chunk with fully hoisted addressing: per element just pointer adds.
__device__ __forceinline__ void stage_chunk(float* __restrict__ buf,
        const float* __restrict__ rubb0,   // rubin + b*Dn*HWn + y0*Wn + x0
        const float* __restrict__ visb0,   // vis   + b*Dn*HWn
        int d0,
        const int (&vgo)[4], const int (&vso)[4], int nvo,
        int rgo, int rso, int dhalf)
{
    const float* visb = visb0 + (size_t)d0 * HWn;
    #pragma unroll
    for (int d = 0; d < DC; ++d) {
        float* vb = buf + d*(HY*HXP);
        const float* vg = visb + (size_t)d*HWn;
        #pragma unroll
        for (int j = 0; j < 4; ++j)
            if (j < nvo) cpa4(vb + vso[j], vg + vgo[j]);
    }
    // rubin: each thread stages one float4 quad for 2 channels (dhalf selects which 2)
    const float* rubb = rubb0 + (size_t)(d0 + dhalf*2) * HWn;
    float* rbuf = buf + VIS_ELE + (dhalf*2)*(TY*TXP);
    cpa16(rbuf + rso,            rubb + rgo);
    cpa16(rbuf + (TY*TXP) + rso, rubb + (size_t)HWn + rgo);
}

// Accumulate raw dots for one D-chunk (2 horizontal pixels per thread),
// plus rubin sumsq and owned-vis sumsq. All smem reads are LDS.64.
__device__ __forceinline__ void compute_chunk(const float* __restrict__ buf,
        int ty, int tx2,
        float (&acc0)[Kn], float (&acc1)[Kn],
        float& ss0, float& ss1,
        float (&vss)[4], const int (&vso)[4], int nvo)
{
    const float* rub = buf + VIS_ELE;
    #pragma unroll
    for (int d = 0; d < DC; ++d) {
        float2 ru = *(const float2*)(rub + d*(TY*TXP) + ty*TXP + tx2);
        const float rx = ru.x, ry = ru.y;
        ss0 = fmaf(rx, rx, ss0);
        ss1 = fmaf(ry, ry, ss1);
        const float* vplane = buf + d*(HY*HXP);
        #pragma unroll
        for (int r = 0; r < 7; ++r) {
            const float2* vr = (const float2*)(vplane + (ty + r)*HXP + tx2);
            float2 p0 = vr[0], p1 = vr[1], p2 = vr[2], p3 = vr[3];
            const int kb = r*7;
            acc0[kb+0] = fmaf(rx, p0.x, acc0[kb+0]);
            acc1[kb+0] = fmaf(ry, p0.y, acc1[kb+0]);
            acc0[kb+1] = fmaf(rx, p0.y, acc0[kb+1]);
            acc1[kb+1] = fmaf(ry, p1.x, acc1[kb+1]);
            acc0[kb+2] = fmaf(rx, p1.x, acc0[kb+2]);
            acc1[kb+2] = fmaf(ry, p1.y, acc1[kb+2]);
            acc0[kb+3] = fmaf(rx, p1.y, acc0[kb+3]);
            acc1[kb+3] = fmaf(ry, p2.x, acc1[kb+3]);
            acc0[kb+4] = fmaf(rx, p2.x, acc0[kb+4]);
            acc1[kb+4] = fmaf(ry, p2.y, acc1[kb+4]);
            acc0[kb+5] = fmaf(rx, p2.y, acc0[kb+5]);
            acc1[kb+5] = fmaf(ry, p3.x, acc1[kb+5]);
            acc0[kb+6] = fmaf(rx, p3.x, acc0[kb+6]);
            acc1[kb+6] = fmaf(ry, p3.y, acc1[kb+6]);
        }
        #pragma unroll
        for (int j = 0; j < 4; ++j)
            if (j < nvo) {
                float v = vplane[vso[j]];
                vss[j] = fmaf(v, v, vss[j]);
            }
    }
}

__device__ __forceinline__ void pixel_post(const float (&l)[Kn], float itau,
        float& dyl, float& dxl, float& conf)
{
    float m = l[0];
    #pragma unroll
    for (int k = 1; k < Kn; ++k) m = fmaxf(m, l[k]);
    float s = 0.f, wy = 0.f, wx = 0.f;
    #pragma unroll
    for (int k = 0; k < Kn; ++k) {
        float e = __expf((l[k] - m)*itau);
        s += e;
        wy += e * (float)(k/7 - 3);
        wx += e * (float)(k%7 - 3);
    }
    float is = 1.f/s;
    conf = is;          // exp(0)=1 at the max -> max prob = 1/sum
    dyl = wy*is;
    dxl = wx*is;
}

__global__ void __launch_bounds__(256)
ccb_main_kernel(const float* __restrict__ rubin, const float* __restrict__ vis,
                const float* __restrict__ logt, float* __restrict__ out)
{
    __shared__ float sm[2*BUF_ELE];
    float* buf0 = sm;
    float* buf1 = sm + BUF_ELE;
    // aliases onto buf0, used only after the main loop:
    float* vinv  = sm;            // HY*HXP = 880 floats
    float* sredw = sm + 880;      // 8 warps * 49 = 392 floats

    const int tx = threadIdx.x, ty = threadIdx.y;
    const int tid = ty*16 + tx;
    const int x0 = blockIdx.x*TX, y0 = blockIdx.y*TY, b = blockIdx.z;
    const int tx2 = 2*tx;

    // ---- hoisted staging addresses (chunk-invariant) ----
    const int nvo = (tid < (NVV - 3*256)) ? 4 : 3;   // 836 = 3*256 + 68
    int vgo[4], vso[4];
    #pragma unroll
    for (int j = 0; j < 4; ++j) {
        int v = tid + 256*j;
        int row = v / HX;
        int col = v - row*HX;
        int gy = min(Hn-1, max(0, y0 - 3 + row));
        int gx = min(Wn-1, max(0, x0 - 3 + col));
        vgo[j] = gy*Wn + gx;
        vso[j] = row*HXP + col;
    }
    const int quad = tid & 127, dhalf = tid >> 7;
    const int rr = quad >> 3, rc = (quad & 7) << 2;
    const int rgo = rr*Wn + rc;
    const int rso = rr*TXP + rc;

    const float* rubb0 = rubin + (size_t)b*Dn*HWn + (size_t)y0*Wn + x0;
    const float* visb0 = vis   + (size_t)b*Dn*HWn;

    float acc0[Kn], acc1[Kn];
    #pragma unroll
    for (int k = 0; k < Kn; ++k) { acc0[k] = 0.f; acc1[k] = 0.f; }
    float ss0 = 0.f, ss1 = 0.f;
    float vss[4] = {0.f, 0.f, 0.f, 0.f};

    // ---- software-pipelined chunk loop (cp.async double buffer) ----
    stage_chunk(buf0, rubb0, visb0, 0, vgo, vso, nvo, rgo, rso, dhalf);
    asm volatile("cp.async.commit_group;" ::: "memory");
    #pragma unroll 1
    for (int ch = 0; ch < NCH; ++ch) {
        if (ch + 1 < NCH) {
            stage_chunk(((ch+1) & 1) ? buf1 : buf0, rubb0, visb0, (ch+1)*DC,
                        vgo, vso, nvo, rgo, rso, dhalf);
            asm volatile("cp.async.commit_group;" ::: "memory");
            asm volatile("cp.async.wait_group 1;" ::: "memory");
        } else {
            asm volatile("cp.async.wait_group 0;" ::: "memory");
        }
        __syncthreads();
        compute_chunk((ch & 1) ? buf1 : buf0, ty, tx2, acc0, acc1, ss0, ss1, vss, vso, nvo);
        __syncthreads();
    }

    // Inverse norms (matches reference: x / max(|x|, 1e-6))
    float inv0 = 1.f / fmaxf(sqrtf(ss0), 1e-6f);
    float inv1 = 1.f / fmaxf(sqrtf(ss1), 1e-6f);
    #pragma unroll
    for (int j = 0; j < 4; ++j)
        if (j < nvo) vinv[vso[j]] = 1.f / fmaxf(sqrtf(vss[j]), 1e-6f);
    __syncthreads();

    // Finalize logits: raw_dot * inv|r| * inv|v| * (1/sqrt(D))
    const float s0 = inv0 * 0.125f;
    const float s1 = inv1 * 0.125f;
    #pragma unroll
    for (int r = 0; r < 7; ++r) {
        const float2* vr = (const float2*)(vinv + (ty + r)*HXP + tx2);
        float2 p0 = vr[0], p1 = vr[1], p2 = vr[2], p3 = vr[3];
        const int kb = r*7;
        acc0[kb+0] *= s0 * p0.x;  acc1[kb+0] *= s1 * p0.y;
        acc0[kb+1] *= s0 * p0.y;  acc1[kb+1] *= s1 * p1.x;
        acc0[kb+2] *= s0 * p1.x;  acc1[kb+2] *= s1 * p1.y;
        acc0[kb+3] *= s0 * p1.y;  acc1[kb+3] *= s1 * p2.x;
        acc0[kb+4] *= s0 * p2.x;  acc1[kb+4] *= s1 * p2.y;
        acc0[kb+5] *= s0 * p2.y;  acc1[kb+5] *= s1 * p3.x;
        acc0[kb+6] *= s0 * p3.x;  acc1[kb+6] *= s1 * p3.y;
    }

    // Write logits (B,K,H,W), coalesced float2 per k
    {
        const size_t base = OFF_LG + (size_t)b*Kn*HWn + (size_t)(y0+ty)*Wn + (x0 + tx2);
        #pragma unroll
        for (int k = 0; k < Kn; ++k) {
            *(float2*)(out + base + (size_t)k*HWn) = make_float2(acc0[k], acc1[k]);
        }
    }

    // Deterministic per-block per-k sums for the global mean
    {
        const int lane = tid & 31, w = tid >> 5;
        #pragma unroll
        for (int k = 0; k < Kn; ++k) {
            float s = acc0[k] + acc1[k];
            s += __shfl_down_sync(0xffffffffu, s, 16);
            s += __shfl_down_sync(0xffffffffu, s, 8);
            s += __shfl_down_sync(0xffffffffu, s, 4);
            s += __shfl_down_sync(0xffffffffu, s, 2);
            s += __shfl_down_sync(0xffffffffu, s, 1);
            if (lane == 0) sredw[w*Kn + k] = s;
        }
        __syncthreads();
        if (tid < Kn) {
            float t = 0.f;
            #pragma unroll
            for (int w2 = 0; w2 < 8; ++w2) t += sredw[w2*Kn + tid];
            int blk = (b*TILES_Y + blockIdx.y)*TILES_X + blockIdx.x;
            g_part[(size_t)blk*Kn + tid] = t;
        }
    }

    // Local softmax / dy / dx / conf / local_weight
    const float tau  = fmaxf(__expf(logt[0]), 1e-3f);
    const float itau = 1.f / tau;
    const float uni  = 1.0f / (float)Kn;
    const float ilw  = 1.0f / (1.0f - uni);

    float dyl0, dxl0, cf0, dyl1, dxl1, cf1;
    pixel_post(acc0, itau, dyl0, dxl0, cf0);
    pixel_post(acc1, itau, dyl1, dxl1, cf1);

    float lw0 = fminf(fmaxf((cf0 - uni)*ilw, 0.f), 1.f);
    float lw1 = fminf(fmaxf((cf1 - uni)*ilw, 0.f), 1.f);

    const size_t pix = (size_t)b*HWn + (size_t)(y0+ty)*Wn + (x0 + tx2);
    *(float2*)(out + OFF_DY + pix) = make_float2(dyl0, dyl1);  // local; blended by kernel 3
    *(float2*)(out + OFF_DX + pix) = make_float2(dxl0, dxl1);
    *(float2*)(out + OFF_CL + pix) = make_float2(cf0, cf1);
    *(float2*)(out + OFF_LW + pix) = make_float2(lw0, lw1);
}

__global__ void ccb_global_kernel(const float* __restrict__ logt, float* __restrict__ out)
{
    const int b = blockIdx.x;
    const int tid = threadIdx.x;   // 64 threads
    __shared__ float lg[Kn];
    if (tid < Kn) {
        float s = 0.f;
        const float* p = g_part + (size_t)(b*TILES_PER_B)*Kn + tid;
        #pragma unroll 4
        for (int t = 0; t < TILES_PER_B; ++t) s += p[(size_t)t*Kn];
        lg[tid] = s * (1.0f/(float)HWn);
    }
    __syncthreads();
    if (tid == 0) {
        const float tau  = fmaxf(__expf(logt[0]), 1e-3f);
        const float itau = 1.f / tau;
        float m = lg[0];
        #pragma unroll
        for (int k = 1; k < Kn; ++k) m = fmaxf(m, lg[k]);
        float s = 0.f, wy = 0.f, wx = 0.f;
        #pragma unroll
        for (int k = 0; k < Kn; ++k) {
            float e = __expf((lg[k] - m)*itau);
            s += e;
            wy += e * (float)(k/7 - 3);
            wx += e * (float)(k%7 - 3);
        }
        float is = 1.f/s;
        out[OFF_CG + b] = is;       // conf_global
        g_dyg[b] = wy*is;
        g_dxg[b] = wx*is;
    }
}

__global__ void ccb_blend_kernel(float* __restrict__ out)
{
    int i = blockIdx.x*blockDim.x + threadIdx.x;
    if (i >= Pn) return;
    int b = i >> 16;               // HWn = 65536
    float lw = out[OFF_LW + i];
    float gw = 1.0f - lw;
    out[OFF_DY + i] = lw*out[OFF_DY + i] + gw*g_dyg[b];
    out[OFF_DX + i] = lw*out[OFF_DX + i] + gw*g_dxg[b];
}

extern "C" void kernel_launch(void* const* d_in, const int* in_sizes, int n_in,
                              void* d_out, int out_size) {
    const float* rubin = (const float*)d_in[0];
    const float* vis   = (const float*)d_in[1];
    const float* logt  = (const float*)d_in[2];
    float* out = (float*)d_out;
    (void)in_sizes; (void)n_in; (void)out_size;

    dim3 grid(TILES_X, TILES_Y, Bn);
    dim3 blk(16, 16, 1);
    ccb_main_kernel<<<grid, blk>>>(rubin, vis, logt, out);
    ccb_global_kernel<<<Bn, 64>>>(logt, out);
    ccb_blend_kernel<<<Pn/256, 256>>>(out);
}